// round 1
// baseline (speedup 1.0000x reference)
#include <cuda_runtime.h>

#define NU 100000
#define NI 50000
#define NN 150000           // NU + NI
#define D  64
#define MAXE 1500000        // interactions
#define NB 147              // ceil(NN / 1024)

// ---------------- scratch (static device globals; no runtime allocation) ----
__device__ float g_rep [NN * D];      // layer input
__device__ float g_rep2[NN * D];      // layer output (ping-pong)
__device__ float g_acc [NN * D];      // running sum over layers
__device__ int   g_deg [NN];
__device__ float g_dinv[NN];
__device__ int   g_offs[NN + 1];      // CSR row offsets (by dst)
__device__ int   g_cursor[NN];
__device__ int   g_col[2 * MAXE];     // CSR src index
__device__ float g_val[2 * MAXE];     // CSR edge weight (norm)
__device__ int   g_bsums[NB];
__device__ int   g_bscan[NB];

// ---------------- setup kernels --------------------------------------------
__global__ void k_zero_deg() {
    int i = blockIdx.x * blockDim.x + threadIdx.x;
    if (i < NN) g_deg[i] = 0;
}

__global__ void k_count_deg(const int* __restrict__ eu,
                            const int* __restrict__ ei, int ne) {
    int e = blockIdx.x * blockDim.x + threadIdx.x;
    if (e >= ne) return;
    atomicAdd(&g_deg[eu[e]], 1);            // dst = user (item->user edge)
    atomicAdd(&g_deg[NU + ei[e]], 1);       // dst = item (user->item edge)
}

__global__ void k_dinv() {
    int i = blockIdx.x * blockDim.x + threadIdx.x;
    if (i >= NN) return;
    int d = g_deg[i];
    g_dinv[i] = rsqrtf(d > 0 ? (float)d : 1.0f);
}

// Block-local exclusive scan (1024 elems per block)
__global__ void k_scan_a(int n) {
    __shared__ int sh[1024];
    int tid = threadIdx.x;
    int i = blockIdx.x * 1024 + tid;
    int v = (i < n) ? g_deg[i] : 0;
    sh[tid] = v;
    __syncthreads();
    for (int off = 1; off < 1024; off <<= 1) {
        int t = (tid >= off) ? sh[tid - off] : 0;
        __syncthreads();
        sh[tid] += t;
        __syncthreads();
    }
    if (i < n) g_offs[i] = sh[tid] - v;     // exclusive within block
    if (tid == 1023) g_bsums[blockIdx.x] = sh[1023];
}

// Scan of block sums (single block)
__global__ void k_scan_b(int nb, int n) {
    __shared__ int sh[1024];
    int tid = threadIdx.x;
    int v = (tid < nb) ? g_bsums[tid] : 0;
    sh[tid] = v;
    __syncthreads();
    for (int off = 1; off < 1024; off <<= 1) {
        int t = (tid >= off) ? sh[tid - off] : 0;
        __syncthreads();
        sh[tid] += t;
        __syncthreads();
    }
    if (tid < nb) g_bscan[tid] = sh[tid] - v;
    if (tid == nb - 1) g_offs[n] = sh[tid];   // grand total
}

__global__ void k_scan_c(int n) {
    int i = blockIdx.x * 1024 + threadIdx.x;
    if (i < n) {
        int o = g_offs[i] + g_bscan[blockIdx.x];
        g_offs[i] = o;
        g_cursor[i] = o;
    }
}

__global__ void k_fill_csr(const int* __restrict__ eu,
                           const int* __restrict__ ei, int ne) {
    int e = blockIdx.x * blockDim.x + threadIdx.x;
    if (e >= ne) return;
    int u  = eu[e];
    int it = NU + ei[e];
    float w = g_dinv[u] * g_dinv[it];
    // edge user -> item  (dst = item)
    int s1 = atomicAdd(&g_cursor[it], 1);
    g_col[s1] = u;  g_val[s1] = w;
    // edge item -> user  (dst = user)
    int s2 = atomicAdd(&g_cursor[u], 1);
    g_col[s2] = it; g_val[s2] = w;
}

__global__ void k_init_rep(const float4* __restrict__ emb, int n4) {
    int i = blockIdx.x * blockDim.x + threadIdx.x;
    if (i >= n4) return;
    float4 v = emb[i];
    reinterpret_cast<float4*>(g_rep)[i] = v;
    reinterpret_cast<float4*>(g_acc)[i] = v;
}

// ---------------- SpMM: one warp per node, register accumulation -----------
// rep_next[v] = sum_{e: dst=v} w_e * rep[src_e];  acc[v] += rep_next[v]
__global__ void k_spmm(int flip, int last) {
    int warp = (blockIdx.x * blockDim.x + threadIdx.x) >> 5;
    if (warp >= NN) return;
    int lane = threadIdx.x & 31;

    const float* __restrict__ rep  = flip ? g_rep2 : g_rep;
    float*       __restrict__ repn = flip ? g_rep  : g_rep2;

    int beg = g_offs[warp];
    int end = g_offs[warp + 1];

    float sx = 0.f, sy = 0.f;
    int j = beg;
    // 4-way unroll for memory-level parallelism
    for (; j + 3 < end; j += 4) {
        int   s0 = g_col[j],   s1 = g_col[j+1], s2 = g_col[j+2], s3 = g_col[j+3];
        float w0 = g_val[j],   w1 = g_val[j+1], w2 = g_val[j+2], w3 = g_val[j+3];
        float2 r0 = *(const float2*)(rep + s0 * D + lane * 2);
        float2 r1 = *(const float2*)(rep + s1 * D + lane * 2);
        float2 r2 = *(const float2*)(rep + s2 * D + lane * 2);
        float2 r3 = *(const float2*)(rep + s3 * D + lane * 2);
        sx = fmaf(w0, r0.x, sx); sy = fmaf(w0, r0.y, sy);
        sx = fmaf(w1, r1.x, sx); sy = fmaf(w1, r1.y, sy);
        sx = fmaf(w2, r2.x, sx); sy = fmaf(w2, r2.y, sy);
        sx = fmaf(w3, r3.x, sx); sy = fmaf(w3, r3.y, sy);
    }
    for (; j < end; j++) {
        int   s = g_col[j];
        float w = g_val[j];
        float2 r = *(const float2*)(rep + s * D + lane * 2);
        sx = fmaf(w, r.x, sx); sy = fmaf(w, r.y, sy);
    }

    int o = warp * D + lane * 2;
    if (!last) *(float2*)(repn + o) = make_float2(sx, sy);
    float2* ap = (float2*)(g_acc + o);
    float2 a = *ap;
    a.x += sx; a.y += sy;
    *ap = a;
}

// ---------------- epilogue: batch gathers + L2 norms -----------------------
__global__ void k_output(const int* __restrict__ users,
                         const int* __restrict__ pos,
                         const int* __restrict__ neg,
                         const float* __restrict__ emb,
                         float* __restrict__ out, int batch) {
    int warp = (blockIdx.x * blockDim.x + threadIdx.x) >> 5;
    if (warp >= batch) return;
    int lane = threadIdx.x & 31;

    int u = users[warp];
    int p = NU + pos[warp];
    int g = NU + neg[warp];

    const float inv = 0.25f;   // 1 / (N_LAYERS + 1)
    int c = lane * 2;

    float2 au = *(const float2*)(g_acc + u * D + c);
    float2 ap = *(const float2*)(g_acc + p * D + c);
    float2 an = *(const float2*)(g_acc + g * D + c);

    *(float2*)(out + (size_t)warp * D + c)                        = make_float2(au.x * inv, au.y * inv);
    *(float2*)(out + (size_t)batch * D + (size_t)warp * D + c)    = make_float2(ap.x * inv, ap.y * inv);
    *(float2*)(out + (size_t)2 * batch * D + (size_t)warp * D + c)= make_float2(an.x * inv, an.y * inv);

    float2 eu = *(const float2*)(emb + (size_t)u * D + c);
    float2 ep = *(const float2*)(emb + (size_t)p * D + c);
    float2 en = *(const float2*)(emb + (size_t)g * D + c);
    float part = eu.x * eu.x + eu.y * eu.y
               + ep.x * ep.x + ep.y * ep.y
               + en.x * en.x + en.y * en.y;
    #pragma unroll
    for (int off = 16; off > 0; off >>= 1)
        part += __shfl_down_sync(0xffffffffu, part, off);
    if (lane == 0)
        out[(size_t)3 * batch * D + warp] = part;
}

// ---------------- launch ----------------------------------------------------
extern "C" void kernel_launch(void* const* d_in, const int* in_sizes, int n_in,
                              void* d_out, int out_size) {
    const float* emb   = (const float*)d_in[0];
    const int*   eu    = (const int*)  d_in[1];
    const int*   ei    = (const int*)  d_in[2];
    const int*   users = (const int*)  d_in[3];
    const int*   pos   = (const int*)  d_in[4];
    const int*   neg   = (const int*)  d_in[5];
    int ne    = in_sizes[1];
    int batch = in_sizes[3];
    float* out = (float*)d_out;

    // 1) degrees
    k_zero_deg<<<(NN + 255) / 256, 256>>>();
    k_count_deg<<<(ne + 255) / 256, 256>>>(eu, ei, ne);
    k_dinv<<<(NN + 255) / 256, 256>>>();

    // 2) CSR offsets via 2-level scan, then cursor = offsets
    k_scan_a<<<NB, 1024>>>(NN);
    k_scan_b<<<1, 1024>>>(NB, NN);
    k_scan_c<<<NB, 1024>>>(NN);

    // 3) CSR fill
    k_fill_csr<<<(ne + 255) / 256, 256>>>(eu, ei, ne);

    // 4) rep = acc = embedding
    int n4 = NN * D / 4;
    k_init_rep<<<(n4 + 255) / 256, 256>>>((const float4*)emb, n4);

    // 5) three propagation layers (gather-based, warp per node)
    int spmm_blocks = (NN * 32 + 255) / 256;
    k_spmm<<<spmm_blocks, 256>>>(0, 0);   // g_rep  -> g_rep2
    k_spmm<<<spmm_blocks, 256>>>(1, 0);   // g_rep2 -> g_rep
    k_spmm<<<spmm_blocks, 256>>>(0, 1);   // g_rep  -> (acc only)

    // 6) epilogue
    k_output<<<(batch * 32 + 255) / 256, 256>>>(users, pos, neg, emb, out, batch);
}

// round 2
// speedup vs baseline: 1.0842x; 1.0842x over previous
#include <cuda_runtime.h>

#define NU 100000
#define NI 50000
#define NN 150000           // NU + NI
#define D  64
#define MAXE 1500000        // interactions
#define NB 147              // ceil(NN / 1024)

// ---------------- scratch (static device globals) ---------------------------
__device__ float g_r1[NN * D];        // layer 1 output
__device__ float g_r2[NN * D];        // layer 2 output
__device__ float g_r3[NN * D];        // layer 3 output
__device__ int   g_deg [NN];
__device__ float g_dinv[NN];
__device__ int   g_offs[NN + 1];      // CSR row offsets (by dst)
__device__ int   g_cursor[NN];
__device__ int2  g_cv[2 * MAXE];      // packed {src, weight-bits}
__device__ int   g_bsums[NB];
__device__ int   g_bscan[NB];

// ---------------- setup ------------------------------------------------------
__global__ void k_zero_deg() {
    int i = blockIdx.x * blockDim.x + threadIdx.x;
    if (i < NN) g_deg[i] = 0;
}

__global__ void k_count_deg(const int* __restrict__ eu,
                            const int* __restrict__ ei, int ne) {
    int e = blockIdx.x * blockDim.x + threadIdx.x;
    if (e >= ne) return;
    atomicAdd(&g_deg[eu[e]], 1);
    atomicAdd(&g_deg[NU + ei[e]], 1);
}

__global__ void k_dinv() {
    int i = blockIdx.x * blockDim.x + threadIdx.x;
    if (i >= NN) return;
    int d = g_deg[i];
    g_dinv[i] = rsqrtf(d > 0 ? (float)d : 1.0f);
}

__global__ void k_scan_a(int n) {
    __shared__ int sh[1024];
    int tid = threadIdx.x;
    int i = blockIdx.x * 1024 + tid;
    int v = (i < n) ? g_deg[i] : 0;
    sh[tid] = v;
    __syncthreads();
    for (int off = 1; off < 1024; off <<= 1) {
        int t = (tid >= off) ? sh[tid - off] : 0;
        __syncthreads();
        sh[tid] += t;
        __syncthreads();
    }
    if (i < n) g_offs[i] = sh[tid] - v;
    if (tid == 1023) g_bsums[blockIdx.x] = sh[1023];
}

__global__ void k_scan_b(int nb, int n) {
    __shared__ int sh[1024];
    int tid = threadIdx.x;
    int v = (tid < nb) ? g_bsums[tid] : 0;
    sh[tid] = v;
    __syncthreads();
    for (int off = 1; off < 1024; off <<= 1) {
        int t = (tid >= off) ? sh[tid - off] : 0;
        __syncthreads();
        sh[tid] += t;
        __syncthreads();
    }
    if (tid < nb) g_bscan[tid] = sh[tid] - v;
    if (tid == nb - 1) g_offs[n] = sh[tid];
}

__global__ void k_scan_c(int n) {
    int i = blockIdx.x * 1024 + threadIdx.x;
    if (i < n) {
        int o = g_offs[i] + g_bscan[blockIdx.x];
        g_offs[i] = o;
        g_cursor[i] = o;
    }
}

__global__ void k_fill_csr(const int* __restrict__ eu,
                           const int* __restrict__ ei, int ne) {
    int e = blockIdx.x * blockDim.x + threadIdx.x;
    if (e >= ne) return;
    int u  = eu[e];
    int it = NU + ei[e];
    float w = g_dinv[u] * g_dinv[it];
    int wb = __float_as_int(w);
    int s1 = atomicAdd(&g_cursor[it], 1);
    g_cv[s1] = make_int2(u, wb);            // edge user -> item (dst=item)
    int s2 = atomicAdd(&g_cursor[u], 1);
    g_cv[s2] = make_int2(it, wb);           // edge item -> user (dst=user)
}

// ---------------- SpMM: one warp per node, register accumulation ------------
// dst[v] = sum_{e: dst=v} w_e * src[col_e]
__global__ void k_spmm(const float* __restrict__ ext_src, int layer) {
    int warp = (blockIdx.x * blockDim.x + threadIdx.x) >> 5;
    if (warp >= NN) return;
    int lane = threadIdx.x & 31;

    const float* __restrict__ src =
        (layer == 0) ? ext_src : ((layer == 1) ? g_r1 : g_r2);
    float* __restrict__ dst =
        (layer == 0) ? g_r1 : ((layer == 1) ? g_r2 : g_r3);

    int beg = g_offs[warp];
    int end = g_offs[warp + 1];

    float sx = 0.f, sy = 0.f;
    int c = lane * 2;
    int j = beg;
    for (; j + 3 < end; j += 4) {
        int2 cv0 = g_cv[j],   cv1 = g_cv[j+1];
        int2 cv2 = g_cv[j+2], cv3 = g_cv[j+3];
        float2 r0 = *(const float2*)(src + cv0.x * D + c);
        float2 r1 = *(const float2*)(src + cv1.x * D + c);
        float2 r2 = *(const float2*)(src + cv2.x * D + c);
        float2 r3 = *(const float2*)(src + cv3.x * D + c);
        float w0 = __int_as_float(cv0.y), w1 = __int_as_float(cv1.y);
        float w2 = __int_as_float(cv2.y), w3 = __int_as_float(cv3.y);
        sx = fmaf(w0, r0.x, sx); sy = fmaf(w0, r0.y, sy);
        sx = fmaf(w1, r1.x, sx); sy = fmaf(w1, r1.y, sy);
        sx = fmaf(w2, r2.x, sx); sy = fmaf(w2, r2.y, sy);
        sx = fmaf(w3, r3.x, sx); sy = fmaf(w3, r3.y, sy);
    }
    for (; j < end; j++) {
        int2 cv = g_cv[j];
        float2 r = *(const float2*)(src + cv.x * D + c);
        float w = __int_as_float(cv.y);
        sx = fmaf(w, r.x, sx); sy = fmaf(w, r.y, sy);
    }
    *(float2*)(dst + warp * D + c) = make_float2(sx, sy);
}

// ---------------- epilogue ---------------------------------------------------
// final_rep = (emb + r1 + r2 + r3) / 4 at sampled nodes; l2 from emb
__global__ void k_output(const int* __restrict__ users,
                         const int* __restrict__ pos,
                         const int* __restrict__ neg,
                         const float* __restrict__ emb,
                         float* __restrict__ out, int batch) {
    int warp = (blockIdx.x * blockDim.x + threadIdx.x) >> 5;
    if (warp >= batch) return;
    int lane = threadIdx.x & 31;

    int u = users[warp];
    int p = NU + pos[warp];
    int g = NU + neg[warp];
    int c = lane * 2;
    const float inv = 0.25f;

    // ---- user
    float2 eu = *(const float2*)(emb  + (size_t)u * D + c);
    float2 a1 = *(const float2*)(g_r1 + u * D + c);
    float2 a2 = *(const float2*)(g_r2 + u * D + c);
    float2 a3 = *(const float2*)(g_r3 + u * D + c);
    float2 fu = make_float2((eu.x + a1.x + a2.x + a3.x) * inv,
                            (eu.y + a1.y + a2.y + a3.y) * inv);
    *(float2*)(out + (size_t)warp * D + c) = fu;

    // ---- pos item
    float2 ep = *(const float2*)(emb  + (size_t)p * D + c);
    float2 b1 = *(const float2*)(g_r1 + p * D + c);
    float2 b2 = *(const float2*)(g_r2 + p * D + c);
    float2 b3 = *(const float2*)(g_r3 + p * D + c);
    float2 fp = make_float2((ep.x + b1.x + b2.x + b3.x) * inv,
                            (ep.y + b1.y + b2.y + b3.y) * inv);
    *(float2*)(out + (size_t)batch * D + (size_t)warp * D + c) = fp;

    // ---- neg item
    float2 en = *(const float2*)(emb  + (size_t)g * D + c);
    float2 c1 = *(const float2*)(g_r1 + g * D + c);
    float2 c2 = *(const float2*)(g_r2 + g * D + c);
    float2 c3 = *(const float2*)(g_r3 + g * D + c);
    float2 fn = make_float2((en.x + c1.x + c2.x + c3.x) * inv,
                            (en.y + c1.y + c2.y + c3.y) * inv);
    *(float2*)(out + (size_t)2 * batch * D + (size_t)warp * D + c) = fn;

    // ---- l2 norm of raw embeddings
    float part = eu.x * eu.x + eu.y * eu.y
               + ep.x * ep.x + ep.y * ep.y
               + en.x * en.x + en.y * en.y;
    #pragma unroll
    for (int off = 16; off > 0; off >>= 1)
        part += __shfl_down_sync(0xffffffffu, part, off);
    if (lane == 0)
        out[(size_t)3 * batch * D + warp] = part;
}

// ---------------- launch -----------------------------------------------------
extern "C" void kernel_launch(void* const* d_in, const int* in_sizes, int n_in,
                              void* d_out, int out_size) {
    const float* emb   = (const float*)d_in[0];
    const int*   eu    = (const int*)  d_in[1];
    const int*   ei    = (const int*)  d_in[2];
    const int*   users = (const int*)  d_in[3];
    const int*   pos   = (const int*)  d_in[4];
    const int*   neg   = (const int*)  d_in[5];
    int ne    = in_sizes[1];
    int batch = in_sizes[3];
    float* out = (float*)d_out;

    // 1) degrees + dinv
    k_zero_deg<<<(NN + 255) / 256, 256>>>();
    k_count_deg<<<(ne + 255) / 256, 256>>>(eu, ei, ne);
    k_dinv<<<(NN + 255) / 256, 256>>>();

    // 2) CSR offsets (2-level scan) + cursors
    k_scan_a<<<NB, 1024>>>(NN);
    k_scan_b<<<1, 1024>>>(NB, NN);
    k_scan_c<<<NB, 1024>>>(NN);

    // 3) CSR fill (packed col+val)
    k_fill_csr<<<(ne + 255) / 256, 256>>>(eu, ei, ne);

    // 4) three propagation layers; layer 1 gathers directly from embedding
    int spmm_blocks = (NN * 32 + 255) / 256;
    k_spmm<<<spmm_blocks, 256>>>(emb, 0);   // emb  -> r1
    k_spmm<<<spmm_blocks, 256>>>(emb, 1);   // r1   -> r2
    k_spmm<<<spmm_blocks, 256>>>(emb, 2);   // r2   -> r3

    // 5) epilogue: fold (emb + r1 + r2 + r3)/4 at sampled nodes + l2 norms
    k_output<<<(batch * 32 + 255) / 256, 256>>>(users, pos, neg, emb, out, batch);
}

// round 4
// speedup vs baseline: 1.1842x; 1.0922x over previous
#include <cuda_runtime.h>
#include <cuda_fp16.h>

#define NU 100000
#define NI 50000
#define NN 150000           // NU + NI
#define D  64
#define MAXE 1500000        // interactions
#define NB 147              // ceil(NN / 1024)

// ---------------- scratch (static device globals) ---------------------------
__device__ float   g_r1[NN * D];       // layer outputs, fp32 (epilogue-exact)
__device__ float   g_r2[NN * D];
__device__ float   g_r3[NN * D];
__device__ __half2 g_h1[NN * D / 2];   // fp16 copies for cheap gathering
__device__ __half2 g_h2[NN * D / 2];
__device__ int     g_deg [NN];
__device__ float   g_dinv[NN];
__device__ int     g_offs[NN + 1];     // CSR row offsets (by dst)
__device__ int     g_cursor[NN];
__device__ int2    g_cv[2 * MAXE];     // packed {src, weight-bits}
__device__ int     g_bsums[NB];
__device__ int     g_bscan[NB];

// ---------------- setup ------------------------------------------------------
__global__ void k_zero_deg() {
    int i = blockIdx.x * blockDim.x + threadIdx.x;
    if (i < NN) g_deg[i] = 0;
}

__global__ void k_count_deg(const int* __restrict__ eu,
                            const int* __restrict__ ei, int ne) {
    int e = blockIdx.x * blockDim.x + threadIdx.x;
    if (e >= ne) return;
    atomicAdd(&g_deg[eu[e]], 1);
    atomicAdd(&g_deg[NU + ei[e]], 1);
}

__global__ void k_dinv() {
    int i = blockIdx.x * blockDim.x + threadIdx.x;
    if (i >= NN) return;
    int d = g_deg[i];
    g_dinv[i] = rsqrtf(d > 0 ? (float)d : 1.0f);
}

__global__ void k_scan_a(int n) {
    __shared__ int sh[1024];
    int tid = threadIdx.x;
    int i = blockIdx.x * 1024 + tid;
    int v = (i < n) ? g_deg[i] : 0;
    sh[tid] = v;
    __syncthreads();
    for (int off = 1; off < 1024; off <<= 1) {
        int t = (tid >= off) ? sh[tid - off] : 0;
        __syncthreads();
        sh[tid] += t;
        __syncthreads();
    }
    if (i < n) g_offs[i] = sh[tid] - v;
    if (tid == 1023) g_bsums[blockIdx.x] = sh[1023];
}

__global__ void k_scan_b(int nb, int n) {
    __shared__ int sh[1024];
    int tid = threadIdx.x;
    int v = (tid < nb) ? g_bsums[tid] : 0;
    sh[tid] = v;
    __syncthreads();
    for (int off = 1; off < 1024; off <<= 1) {
        int t = (tid >= off) ? sh[tid - off] : 0;
        __syncthreads();
        sh[tid] += t;
        __syncthreads();
    }
    if (tid < nb) g_bscan[tid] = sh[tid] - v;
    if (tid == nb - 1) g_offs[n] = sh[tid];
}

__global__ void k_scan_c(int n) {
    int i = blockIdx.x * 1024 + threadIdx.x;
    if (i < n) {
        int o = g_offs[i] + g_bscan[blockIdx.x];
        g_offs[i] = o;
        g_cursor[i] = o;
    }
}

__global__ void k_fill_csr(const int* __restrict__ eu,
                           const int* __restrict__ ei, int ne) {
    int e = blockIdx.x * blockDim.x + threadIdx.x;
    if (e >= ne) return;
    int u  = eu[e];
    int it = NU + ei[e];
    float w = g_dinv[u] * g_dinv[it];
    int wb = __float_as_int(w);
    int s1 = atomicAdd(&g_cursor[it], 1);
    g_cv[s1] = make_int2(u, wb);            // edge user -> item (dst=item)
    int s2 = atomicAdd(&g_cursor[u], 1);
    g_cv[s2] = make_int2(it, wb);           // edge item -> user (dst=user)
}

// ---------------- SpMM: one warp per node, register accumulation ------------
// LAYER 0: fp32 emb (param)  -> g_r1 + g_h1
// LAYER 1: g_h1 (fp16 gather) -> g_r2 + g_h2
// LAYER 2: g_h2 (fp16 gather) -> g_r3
template<int LAYER>
__global__ void k_spmm(const float* __restrict__ emb) {
    int warp = (blockIdx.x * blockDim.x + threadIdx.x) >> 5;
    if (warp >= NN) return;
    int lane = threadIdx.x & 31;

    const __half2* __restrict__ srch = (LAYER == 1) ? g_h1 : g_h2;

    int beg = g_offs[warp];
    int end = g_offs[warp + 1];

    float sx = 0.f, sy = 0.f;
    int j = beg;
    for (; j + 3 < end; j += 4) {
        int2 cv0 = g_cv[j],   cv1 = g_cv[j+1];
        int2 cv2 = g_cv[j+2], cv3 = g_cv[j+3];
        float2 r0, r1, r2, r3;
        if (LAYER == 0) {
            r0 = ((const float2*)emb)[cv0.x * 32 + lane];
            r1 = ((const float2*)emb)[cv1.x * 32 + lane];
            r2 = ((const float2*)emb)[cv2.x * 32 + lane];
            r3 = ((const float2*)emb)[cv3.x * 32 + lane];
        } else {
            r0 = __half22float2(srch[cv0.x * 32 + lane]);
            r1 = __half22float2(srch[cv1.x * 32 + lane]);
            r2 = __half22float2(srch[cv2.x * 32 + lane]);
            r3 = __half22float2(srch[cv3.x * 32 + lane]);
        }
        float w0 = __int_as_float(cv0.y), w1 = __int_as_float(cv1.y);
        float w2 = __int_as_float(cv2.y), w3 = __int_as_float(cv3.y);
        sx = fmaf(w0, r0.x, sx); sy = fmaf(w0, r0.y, sy);
        sx = fmaf(w1, r1.x, sx); sy = fmaf(w1, r1.y, sy);
        sx = fmaf(w2, r2.x, sx); sy = fmaf(w2, r2.y, sy);
        sx = fmaf(w3, r3.x, sx); sy = fmaf(w3, r3.y, sy);
    }
    for (; j < end; j++) {
        int2 cv = g_cv[j];
        float2 r;
        if (LAYER == 0) r = ((const float2*)emb)[cv.x * 32 + lane];
        else            r = __half22float2(srch[cv.x * 32 + lane]);
        float w = __int_as_float(cv.y);
        sx = fmaf(w, r.x, sx); sy = fmaf(w, r.y, sy);
    }

    int o = warp * 32 + lane;
    if (LAYER == 0) {
        ((float2*)g_r1)[o] = make_float2(sx, sy);
        g_h1[o] = __floats2half2_rn(sx, sy);
    } else if (LAYER == 1) {
        ((float2*)g_r2)[o] = make_float2(sx, sy);
        g_h2[o] = __floats2half2_rn(sx, sy);
    } else {
        ((float2*)g_r3)[o] = make_float2(sx, sy);
    }
}

// ---------------- epilogue ---------------------------------------------------
// final_rep = (emb + r1 + r2 + r3) / 4 at sampled nodes; l2 from emb
__global__ void k_output(const int* __restrict__ users,
                         const int* __restrict__ pos,
                         const int* __restrict__ neg,
                         const float* __restrict__ emb,
                         float* __restrict__ out, int batch) {
    int warp = (blockIdx.x * blockDim.x + threadIdx.x) >> 5;
    if (warp >= batch) return;
    int lane = threadIdx.x & 31;

    int u = users[warp];
    int p = NU + pos[warp];
    int g = NU + neg[warp];
    int c = lane * 2;
    const float inv = 0.25f;

    float2 eu = *(const float2*)(emb  + (size_t)u * D + c);
    float2 a1 = *(const float2*)(g_r1 + u * D + c);
    float2 a2 = *(const float2*)(g_r2 + u * D + c);
    float2 a3 = *(const float2*)(g_r3 + u * D + c);
    *(float2*)(out + (size_t)warp * D + c) =
        make_float2((eu.x + a1.x + a2.x + a3.x) * inv,
                    (eu.y + a1.y + a2.y + a3.y) * inv);

    float2 ep = *(const float2*)(emb  + (size_t)p * D + c);
    float2 b1 = *(const float2*)(g_r1 + p * D + c);
    float2 b2 = *(const float2*)(g_r2 + p * D + c);
    float2 b3 = *(const float2*)(g_r3 + p * D + c);
    *(float2*)(out + (size_t)batch * D + (size_t)warp * D + c) =
        make_float2((ep.x + b1.x + b2.x + b3.x) * inv,
                    (ep.y + b1.y + b2.y + b3.y) * inv);

    float2 en = *(const float2*)(emb  + (size_t)g * D + c);
    float2 c1 = *(const float2*)(g_r1 + g * D + c);
    float2 c2 = *(const float2*)(g_r2 + g * D + c);
    float2 c3 = *(const float2*)(g_r3 + g * D + c);
    *(float2*)(out + (size_t)2 * batch * D + (size_t)warp * D + c) =
        make_float2((en.x + c1.x + c2.x + c3.x) * inv,
                    (en.y + c1.y + c2.y + c3.y) * inv);

    float part = eu.x * eu.x + eu.y * eu.y
               + ep.x * ep.x + ep.y * ep.y
               + en.x * en.x + en.y * en.y;
    #pragma unroll
    for (int off = 16; off > 0; off >>= 1)
        part += __shfl_down_sync(0xffffffffu, part, off);
    if (lane == 0)
        out[(size_t)3 * batch * D + warp] = part;
}

// ---------------- launch -----------------------------------------------------
extern "C" void kernel_launch(void* const* d_in, const int* in_sizes, int n_in,
                              void* d_out, int out_size) {
    const float* emb   = (const float*)d_in[0];
    const int*   eu    = (const int*)  d_in[1];
    const int*   ei    = (const int*)  d_in[2];
    const int*   users = (const int*)  d_in[3];
    const int*   pos   = (const int*)  d_in[4];
    const int*   neg   = (const int*)  d_in[5];
    int ne    = in_sizes[1];
    int batch = in_sizes[3];
    float* out = (float*)d_out;

    // 1) degrees + dinv
    k_zero_deg<<<(NN + 255) / 256, 256>>>();
    k_count_deg<<<(ne + 255) / 256, 256>>>(eu, ei, ne);
    k_dinv<<<(NN + 255) / 256, 256>>>();

    // 2) CSR offsets (2-level scan) + cursors
    k_scan_a<<<NB, 1024>>>(NN);
    k_scan_b<<<1, 1024>>>(NB, NN);
    k_scan_c<<<NB, 1024>>>(NN);

    // 3) CSR fill (packed col+val)
    k_fill_csr<<<(ne + 255) / 256, 256>>>(eu, ei, ne);

    // 4) three propagation layers
    int spmm_blocks = (NN * 32 + 255) / 256;
    k_spmm<0><<<spmm_blocks, 256>>>(emb);   // emb -> r1 + h1
    k_spmm<1><<<spmm_blocks, 256>>>(emb);   // h1  -> r2 + h2
    k_spmm<2><<<spmm_blocks, 256>>>(emb);   // h2  -> r3

    // 5) epilogue: fold (emb + r1 + r2 + r3)/4 at sampled nodes + l2 norms
    k_output<<<(batch * 32 + 255) / 256, 256>>>(users, pos, neg, emb, out, batch);
}

// round 6
// speedup vs baseline: 1.2844x; 1.0846x over previous
#include <cuda_runtime.h>
#include <cuda_fp16.h>

#define NU 100000
#define NI 50000
#define NN 150000           // NU + NI
#define D  64
#define MAXE 1500000        // interactions
#define NB 147              // ceil(NN / 1024)

// ---------------- scratch (static device globals) ---------------------------
__device__ float   g_r1[NN * D];       // layer outputs, fp32 (epilogue-exact)
__device__ float   g_r2[NN * D];
__device__ float   g_r3[NN * D];
__device__ __half2 g_h0[NN * D / 2];   // pre-scaled fp16 operands (dinv * rep)
__device__ __half2 g_h1[NN * D / 2];
__device__ __half2 g_h2[NN * D / 2];
__device__ int     g_deg [NN];
__device__ float   g_dinv[NN];
__device__ int     g_offs[NN + 1];     // CSR row offsets (by dst)
__device__ int     g_cursor[NN];
__device__ int     g_col[2 * MAXE];    // CSR src index (weight-free)
__device__ int     g_bsums[NB];
__device__ int     g_bscan[NB];

// ---------------- setup ------------------------------------------------------
__global__ void k_zero_deg() {
    int i = blockIdx.x * blockDim.x + threadIdx.x;
    if (i < NN) g_deg[i] = 0;
}

__global__ void k_count_deg(const int* __restrict__ eu,
                            const int* __restrict__ ei, int ne) {
    int e = blockIdx.x * blockDim.x + threadIdx.x;
    if (e >= ne) return;
    atomicAdd(&g_deg[eu[e]], 1);
    atomicAdd(&g_deg[NU + ei[e]], 1);
}

__global__ void k_dinv() {
    int i = blockIdx.x * blockDim.x + threadIdx.x;
    if (i >= NN) return;
    int d = g_deg[i];
    g_dinv[i] = rsqrtf(d > 0 ? (float)d : 1.0f);
}

__global__ void k_scan_a(int n) {
    __shared__ int sh[1024];
    int tid = threadIdx.x;
    int i = blockIdx.x * 1024 + tid;
    int v = (i < n) ? g_deg[i] : 0;
    sh[tid] = v;
    __syncthreads();
    for (int off = 1; off < 1024; off <<= 1) {
        int t = (tid >= off) ? sh[tid - off] : 0;
        __syncthreads();
        sh[tid] += t;
        __syncthreads();
    }
    if (i < n) g_offs[i] = sh[tid] - v;
    if (tid == 1023) g_bsums[blockIdx.x] = sh[1023];
}

__global__ void k_scan_b(int nb, int n) {
    __shared__ int sh[1024];
    int tid = threadIdx.x;
    int v = (tid < nb) ? g_bsums[tid] : 0;
    sh[tid] = v;
    __syncthreads();
    for (int off = 1; off < 1024; off <<= 1) {
        int t = (tid >= off) ? sh[tid - off] : 0;
        __syncthreads();
        sh[tid] += t;
        __syncthreads();
    }
    if (tid < nb) g_bscan[tid] = sh[tid] - v;
    if (tid == nb - 1) g_offs[n] = sh[tid];
}

__global__ void k_scan_c(int n) {
    int i = blockIdx.x * 1024 + threadIdx.x;
    if (i < n) {
        int o = g_offs[i] + g_bscan[blockIdx.x];
        g_offs[i] = o;
        g_cursor[i] = o;
    }
}

__global__ void k_fill_csr(const int* __restrict__ eu,
                           const int* __restrict__ ei, int ne) {
    int e = blockIdx.x * blockDim.x + threadIdx.x;
    if (e >= ne) return;
    int u  = eu[e];
    int it = NU + ei[e];
    int s1 = atomicAdd(&g_cursor[it], 1);
    g_col[s1] = u;                          // edge user -> item (dst=item)
    int s2 = atomicAdd(&g_cursor[u], 1);
    g_col[s2] = it;                         // edge item -> user (dst=user)
}

// h0[v] = half(emb[v] * dinv[v])   (pre-scaled layer-0 operand)
__global__ void k_prescale(const float* __restrict__ emb) {
    int i = blockIdx.x * blockDim.x + threadIdx.x;   // over NN*32 half2 elems
    if (i >= NN * 32) return;
    int node = i >> 5;
    float dv = g_dinv[node];
    float2 e = ((const float2*)emb)[i];
    g_h0[i] = __floats2half2_rn(e.x * dv, e.y * dv);
}

// ---------------- SpMM: one warp per node, register accumulation ------------
// s = sum_{e: dst=v} y_{l-1}[col_e]   (y pre-scaled by dinv)
// rep_l[v] = dinv[v] * s   (fp32)
// y_l[v]   = half(dinv[v]^2 * s)      (next layer's operand)
template<int LAYER>
__global__ void k_spmm() {
    int warp = (blockIdx.x * blockDim.x + threadIdx.x) >> 5;
    if (warp >= NN) return;
    int lane = threadIdx.x & 31;

    const __half2* __restrict__ srch =
        (LAYER == 0) ? g_h0 : (LAYER == 1) ? g_h1 : g_h2;

    int beg = g_offs[warp];
    int end = g_offs[warp + 1];

    float sx = 0.f, sy = 0.f;
    int j = beg;
    for (; j + 3 < end; j += 4) {
        int s0 = g_col[j],   s1 = g_col[j+1];
        int s2 = g_col[j+2], s3 = g_col[j+3];
        float2 r0 = __half22float2(srch[s0 * 32 + lane]);
        float2 r1 = __half22float2(srch[s1 * 32 + lane]);
        float2 r2 = __half22float2(srch[s2 * 32 + lane]);
        float2 r3 = __half22float2(srch[s3 * 32 + lane]);
        sx += r0.x + r1.x + r2.x + r3.x;
        sy += r0.y + r1.y + r2.y + r3.y;
    }
    for (; j < end; j++) {
        float2 r = __half22float2(srch[g_col[j] * 32 + lane]);
        sx += r.x; sy += r.y;
    }

    float dv = g_dinv[warp];
    float rx = dv * sx, ry = dv * sy;
    int o = warp * 32 + lane;
    if (LAYER == 0) {
        ((float2*)g_r1)[o] = make_float2(rx, ry);
        g_h1[o] = __floats2half2_rn(dv * rx, dv * ry);
    } else if (LAYER == 1) {
        ((float2*)g_r2)[o] = make_float2(rx, ry);
        g_h2[o] = __floats2half2_rn(dv * rx, dv * ry);
    } else {
        ((float2*)g_r3)[o] = make_float2(rx, ry);
    }
}

// ---------------- epilogue ---------------------------------------------------
__global__ void k_output(const int* __restrict__ users,
                         const int* __restrict__ pos,
                         const int* __restrict__ neg,
                         const float* __restrict__ emb,
                         float* __restrict__ out, int batch) {
    int warp = (blockIdx.x * blockDim.x + threadIdx.x) >> 5;
    if (warp >= batch) return;
    int lane = threadIdx.x & 31;

    int u = users[warp];
    int p = NU + pos[warp];
    int g = NU + neg[warp];
    int c = lane * 2;
    const float inv = 0.25f;

    float2 eu = *(const float2*)(emb  + (size_t)u * D + c);
    float2 a1 = *(const float2*)(g_r1 + u * D + c);
    float2 a2 = *(const float2*)(g_r2 + u * D + c);
    float2 a3 = *(const float2*)(g_r3 + u * D + c);
    *(float2*)(out + (size_t)warp * D + c) =
        make_float2((eu.x + a1.x + a2.x + a3.x) * inv,
                    (eu.y + a1.y + a2.y + a3.y) * inv);

    float2 ep = *(const float2*)(emb  + (size_t)p * D + c);
    float2 b1 = *(const float2*)(g_r1 + p * D + c);
    float2 b2 = *(const float2*)(g_r2 + p * D + c);
    float2 b3 = *(const float2*)(g_r3 + p * D + c);
    *(float2*)(out + (size_t)batch * D + (size_t)warp * D + c) =
        make_float2((ep.x + b1.x + b2.x + b3.x) * inv,
                    (ep.y + b1.y + b2.y + b3.y) * inv);

    float2 en = *(const float2*)(emb  + (size_t)g * D + c);
    float2 c1 = *(const float2*)(g_r1 + g * D + c);
    float2 c2 = *(const float2*)(g_r2 + g * D + c);
    float2 c3 = *(const float2*)(g_r3 + g * D + c);
    *(float2*)(out + (size_t)2 * batch * D + (size_t)warp * D + c) =
        make_float2((en.x + c1.x + c2.x + c3.x) * inv,
                    (en.y + c1.y + c2.y + c3.y) * inv);

    float part = eu.x * eu.x + eu.y * eu.y
               + ep.x * ep.x + ep.y * ep.y
               + en.x * en.x + en.y * en.y;
    #pragma unroll
    for (int off = 16; off > 0; off >>= 1)
        part += __shfl_down_sync(0xffffffffu, part, off);
    if (lane == 0)
        out[(size_t)3 * batch * D + warp] = part;
}

// ---------------- launch -----------------------------------------------------
extern "C" void kernel_launch(void* const* d_in, const int* in_sizes, int n_in,
                              void* d_out, int out_size) {
    const float* emb   = (const float*)d_in[0];
    const int*   eu    = (const int*)  d_in[1];
    const int*   ei    = (const int*)  d_in[2];
    const int*   users = (const int*)  d_in[3];
    const int*   pos   = (const int*)  d_in[4];
    const int*   neg   = (const int*)  d_in[5];
    int ne    = in_sizes[1];
    int batch = in_sizes[3];
    float* out = (float*)d_out;

    // 1) degrees + dinv
    k_zero_deg<<<(NN + 255) / 256, 256>>>();
    k_count_deg<<<(ne + 255) / 256, 256>>>(eu, ei, ne);
    k_dinv<<<(NN + 255) / 256, 256>>>();

    // 2) CSR offsets (2-level scan) + cursors
    k_scan_a<<<NB, 1024>>>(NN);
    k_scan_b<<<1, 1024>>>(NB, NN);
    k_scan_c<<<NB, 1024>>>(NN);

    // 3) CSR fill (cols only) + pre-scaled fp16 embedding
    k_fill_csr<<<(ne + 255) / 256, 256>>>(eu, ei, ne);
    k_prescale<<<(NN * 32 + 255) / 256, 256>>>(emb);

    // 4) three propagation layers (all-fp16 gathers, weight-free)
    int spmm_blocks = (NN * 32 + 255) / 256;
    k_spmm<0><<<spmm_blocks, 256>>>();   // h0 -> r1 + h1
    k_spmm<1><<<spmm_blocks, 256>>>();   // h1 -> r2 + h2
    k_spmm<2><<<spmm_blocks, 256>>>();   // h2 -> r3

    // 5) epilogue: fold (emb + r1 + r2 + r3)/4 at sampled nodes + l2 norms
    k_output<<<(batch * 32 + 255) / 256, 256>>>(users, pos, neg, emb, out, batch);
}

// round 7
// speedup vs baseline: 1.3238x; 1.0307x over previous
#include <cuda_runtime.h>
#include <cuda_fp16.h>

#define NU 100000
#define NI 50000
#define NN 150000           // NU + NI
#define D  64
#define MAXE 1500000        // interactions
#define NB 147              // ceil(NN / 1024)

// ---------------- scratch (static device globals) ---------------------------
// y_l = dinv^2 * s  (pre-scaled fp16 operand; r_l = y_l / dinv)
__device__ __half2 g_h0[NN * D / 2];   // layer-0 operand: half(emb * dinv)
__device__ __half2 g_h1[NN * D / 2];
__device__ __half2 g_h2[NN * D / 2];
__device__ __half2 g_h3[NN * D / 2];
__device__ int     g_deg [NN];
__device__ float   g_dinv[NN];
__device__ int     g_offs[NN + 1];     // CSR row offsets (by dst)
__device__ int     g_cursor[NN];
__device__ int     g_col[2 * MAXE];    // CSR src index (weight-free)
__device__ int     g_bsums[NB];
__device__ int     g_bscan[NB];

// ---------------- setup ------------------------------------------------------
__global__ void k_zero_deg() {
    int i = blockIdx.x * blockDim.x + threadIdx.x;
    if (i < NN) g_deg[i] = 0;
}

__global__ void k_count_deg(const int* __restrict__ eu,
                            const int* __restrict__ ei, int ne) {
    int e = blockIdx.x * blockDim.x + threadIdx.x;
    if (e >= ne) return;
    atomicAdd(&g_deg[eu[e]], 1);
    atomicAdd(&g_deg[NU + ei[e]], 1);
}

// scan (part a) + dinv computation fused (both read g_deg)
__global__ void k_scan_a(int n) {
    __shared__ int sh[1024];
    int tid = threadIdx.x;
    int i = blockIdx.x * 1024 + tid;
    int v = (i < n) ? g_deg[i] : 0;
    if (i < n) g_dinv[i] = rsqrtf(v > 0 ? (float)v : 1.0f);
    sh[tid] = v;
    __syncthreads();
    for (int off = 1; off < 1024; off <<= 1) {
        int t = (tid >= off) ? sh[tid - off] : 0;
        __syncthreads();
        sh[tid] += t;
        __syncthreads();
    }
    if (i < n) g_offs[i] = sh[tid] - v;
    if (tid == 1023) g_bsums[blockIdx.x] = sh[1023];
}

__global__ void k_scan_b(int nb, int n) {
    __shared__ int sh[1024];
    int tid = threadIdx.x;
    int v = (tid < nb) ? g_bsums[tid] : 0;
    sh[tid] = v;
    __syncthreads();
    for (int off = 1; off < 1024; off <<= 1) {
        int t = (tid >= off) ? sh[tid - off] : 0;
        __syncthreads();
        sh[tid] += t;
        __syncthreads();
    }
    if (tid < nb) g_bscan[tid] = sh[tid] - v;
    if (tid == nb - 1) g_offs[n] = sh[tid];
}

__global__ void k_scan_c(int n) {
    int i = blockIdx.x * 1024 + threadIdx.x;
    if (i < n) {
        int o = g_offs[i] + g_bscan[blockIdx.x];
        g_offs[i] = o;
        g_cursor[i] = o;
    }
}

__global__ void k_fill_csr(const int* __restrict__ eu,
                           const int* __restrict__ ei, int ne) {
    int e = blockIdx.x * blockDim.x + threadIdx.x;
    if (e >= ne) return;
    int u  = eu[e];
    int it = NU + ei[e];
    int s1 = atomicAdd(&g_cursor[it], 1);
    g_col[s1] = u;                          // edge user -> item (dst=item)
    int s2 = atomicAdd(&g_cursor[u], 1);
    g_col[s2] = it;                         // edge item -> user (dst=user)
}

// h0[v] = half(emb[v] * dinv[v])   (pre-scaled layer-0 operand)
__global__ void k_prescale(const float* __restrict__ emb) {
    int i = blockIdx.x * blockDim.x + threadIdx.x;   // over NN*32 half2 elems
    if (i >= NN * 32) return;
    int node = i >> 5;
    float dv = g_dinv[node];
    float2 e = ((const float2*)emb)[i];
    g_h0[i] = __floats2half2_rn(e.x * dv, e.y * dv);
}

// ---------------- SpMM: one warp per node ------------------------------------
// s = sum_{e: dst=v} y_{l-1}[col_e]
// y_l[v] = half(dinv[v]^2 * s)   (both next layer's operand AND output carrier:
//                                 r_l[v] = y_l[v] / dinv[v])
// cols are loaded coalesced (one per lane per 32-chunk) and shfl-broadcast.
template<int LAYER>
__global__ void k_spmm() {
    int node = (blockIdx.x * blockDim.x + threadIdx.x) >> 5;
    if (node >= NN) return;
    int lane = threadIdx.x & 31;

    const __half2* __restrict__ srch =
        (LAYER == 0) ? g_h0 : (LAYER == 1) ? g_h1 : g_h2;
    __half2* __restrict__ dsth =
        (LAYER == 0) ? g_h1 : (LAYER == 1) ? g_h2 : g_h3;

    int beg = g_offs[node];
    int end = g_offs[node + 1];

    float sx = 0.f, sy = 0.f;
    for (int base = beg; base < end; base += 32) {
        int j = base + lane;
        int mycol = (j < end) ? g_col[j] : 0;       // coalesced, 1 LDG / 32 edges
        int cnt = end - base;
        if (cnt > 32) cnt = 32;
        int i = 0;
        for (; i + 3 < cnt; i += 4) {
            int c0 = __shfl_sync(0xffffffffu, mycol, i);
            int c1 = __shfl_sync(0xffffffffu, mycol, i + 1);
            int c2 = __shfl_sync(0xffffffffu, mycol, i + 2);
            int c3 = __shfl_sync(0xffffffffu, mycol, i + 3);
            float2 r0 = __half22float2(srch[c0 * 32 + lane]);
            float2 r1 = __half22float2(srch[c1 * 32 + lane]);
            float2 r2 = __half22float2(srch[c2 * 32 + lane]);
            float2 r3 = __half22float2(srch[c3 * 32 + lane]);
            sx += r0.x + r1.x + r2.x + r3.x;
            sy += r0.y + r1.y + r2.y + r3.y;
        }
        for (; i < cnt; i++) {
            int c = __shfl_sync(0xffffffffu, mycol, i);
            float2 r = __half22float2(srch[c * 32 + lane]);
            sx += r.x; sy += r.y;
        }
    }

    float dv = g_dinv[node];
    float d2 = dv * dv;
    dsth[node * 32 + lane] = __floats2half2_rn(d2 * sx, d2 * sy);
}

// ---------------- epilogue ---------------------------------------------------
// r_l[v] = y_l[v] / dinv[v];  final = (emb + r1 + r2 + r3) / 4
__global__ void k_output(const int* __restrict__ users,
                         const int* __restrict__ pos,
                         const int* __restrict__ neg,
                         const float* __restrict__ emb,
                         float* __restrict__ out, int batch) {
    int warp = (blockIdx.x * blockDim.x + threadIdx.x) >> 5;
    if (warp >= batch) return;
    int lane = threadIdx.x & 31;

    int idx[3];
    idx[0] = users[warp];
    idx[1] = NU + pos[warp];
    idx[2] = NU + neg[warp];

    float part = 0.f;
    #pragma unroll
    for (int t = 0; t < 3; t++) {
        int v = idx[t];
        int o = v * 32 + lane;
        float sd = 1.0f / g_dinv[v];            // sqrt(deg)
        float2 e  = ((const float2*)emb)[o];
        float2 y1 = __half22float2(g_h1[o]);
        float2 y2 = __half22float2(g_h2[o]);
        float2 y3 = __half22float2(g_h3[o]);
        float fx = (e.x + (y1.x + y2.x + y3.x) * sd) * 0.25f;
        float fy = (e.y + (y1.y + y2.y + y3.y) * sd) * 0.25f;
        ((float2*)out)[(size_t)t * batch * 32 + (size_t)warp * 32 + lane] =
            make_float2(fx, fy);
        part += e.x * e.x + e.y * e.y;
    }

    #pragma unroll
    for (int off = 16; off > 0; off >>= 1)
        part += __shfl_down_sync(0xffffffffu, part, off);
    if (lane == 0)
        out[(size_t)3 * batch * D + warp] = part;
}

// ---------------- launch -----------------------------------------------------
extern "C" void kernel_launch(void* const* d_in, const int* in_sizes, int n_in,
                              void* d_out, int out_size) {
    const float* emb   = (const float*)d_in[0];
    const int*   eu    = (const int*)  d_in[1];
    const int*   ei    = (const int*)  d_in[2];
    const int*   users = (const int*)  d_in[3];
    const int*   pos   = (const int*)  d_in[4];
    const int*   neg   = (const int*)  d_in[5];
    int ne    = in_sizes[1];
    int batch = in_sizes[3];
    float* out = (float*)d_out;

    // 1) degrees
    k_zero_deg<<<(NN + 255) / 256, 256>>>();
    k_count_deg<<<(ne + 255) / 256, 256>>>(eu, ei, ne);

    // 2) CSR offsets (2-level scan, dinv fused into scan_a) + cursors
    k_scan_a<<<NB, 1024>>>(NN);
    k_scan_b<<<1, 1024>>>(NB, NN);
    k_scan_c<<<NB, 1024>>>(NN);

    // 3) CSR fill (cols only) + pre-scaled fp16 embedding
    k_fill_csr<<<(ne + 255) / 256, 256>>>(eu, ei, ne);
    k_prescale<<<(NN * 32 + 255) / 256, 256>>>(emb);

    // 4) three propagation layers (fp16 gathers, shfl-broadcast cols)
    int spmm_blocks = (NN * 32 + 255) / 256;
    k_spmm<0><<<spmm_blocks, 256>>>();   // h0 -> h1
    k_spmm<1><<<spmm_blocks, 256>>>();   // h1 -> h2
    k_spmm<2><<<spmm_blocks, 256>>>();   // h2 -> h3

    // 5) epilogue: reconstruct r_l, fold, l2 norms
    k_output<<<(batch * 32 + 255) / 256, 256>>>(users, pos, neg, emb, out, batch);
}

// round 8
// speedup vs baseline: 1.3914x; 1.0510x over previous
#include <cuda_runtime.h>
#include <cuda_fp16.h>

#define NU 100000
#define NI 50000
#define NN 150000           // NU + NI
#define D  64
#define MAXE 1500000        // interactions
#define NB 147              // ceil(NN / 1024)

// ---------------- scratch (static device globals) ---------------------------
// y_l = dinv^2 * s  (pre-scaled fp16 operand; r_l = y_l / dinv)
__device__ __half2 g_h0[NN * D / 2];   // layer-0 operand: half(emb * dinv)
__device__ __half2 g_h1[NN * D / 2];
__device__ __half2 g_h2[NN * D / 2];
__device__ __half2 g_h3[NN * D / 2];
__device__ int     g_deg [NN];
__device__ float   g_dinv[NN];
__device__ int     g_offs[NN + 1];     // CSR row offsets (by dst)
__device__ int     g_cursor[NN];
__device__ int     g_col[2 * MAXE];    // CSR src index (weight-free)
__device__ int     g_bsums[NB];
__device__ int     g_bscan[NB];

// ---------------- setup ------------------------------------------------------
__global__ void k_zero_deg() {
    int i = blockIdx.x * blockDim.x + threadIdx.x;
    if (i < NN) g_deg[i] = 0;
}

__global__ void k_count_deg(const int* __restrict__ eu,
                            const int* __restrict__ ei, int ne) {
    int e = blockIdx.x * blockDim.x + threadIdx.x;
    if (e >= ne) return;
    atomicAdd(&g_deg[eu[e]], 1);
    atomicAdd(&g_deg[NU + ei[e]], 1);
}

// scan (part a) + dinv computation fused (both read g_deg)
__global__ void k_scan_a(int n) {
    __shared__ int sh[1024];
    int tid = threadIdx.x;
    int i = blockIdx.x * 1024 + tid;
    int v = (i < n) ? g_deg[i] : 0;
    if (i < n) g_dinv[i] = rsqrtf(v > 0 ? (float)v : 1.0f);
    sh[tid] = v;
    __syncthreads();
    for (int off = 1; off < 1024; off <<= 1) {
        int t = (tid >= off) ? sh[tid - off] : 0;
        __syncthreads();
        sh[tid] += t;
        __syncthreads();
    }
    if (i < n) g_offs[i] = sh[tid] - v;
    if (tid == 1023) g_bsums[blockIdx.x] = sh[1023];
}

__global__ void k_scan_b(int nb, int n) {
    __shared__ int sh[1024];
    int tid = threadIdx.x;
    int v = (tid < nb) ? g_bsums[tid] : 0;
    sh[tid] = v;
    __syncthreads();
    for (int off = 1; off < 1024; off <<= 1) {
        int t = (tid >= off) ? sh[tid - off] : 0;
        __syncthreads();
        sh[tid] += t;
        __syncthreads();
    }
    if (tid < nb) g_bscan[tid] = sh[tid] - v;
    if (tid == nb - 1) g_offs[n] = sh[tid];
}

__global__ void k_scan_c(int n) {
    int i = blockIdx.x * 1024 + threadIdx.x;
    if (i < n) {
        int o = g_offs[i] + g_bscan[blockIdx.x];
        g_offs[i] = o;
        g_cursor[i] = o;
    }
}

__global__ void k_fill_csr(const int* __restrict__ eu,
                           const int* __restrict__ ei, int ne) {
    int e = blockIdx.x * blockDim.x + threadIdx.x;
    if (e >= ne) return;
    int u  = eu[e];
    int it = NU + ei[e];
    int s1 = atomicAdd(&g_cursor[it], 1);
    g_col[s1] = u;                          // edge user -> item (dst=item)
    int s2 = atomicAdd(&g_cursor[u], 1);
    g_col[s2] = it;                         // edge item -> user (dst=user)
}

// h0[v] = half(emb[v] * dinv[v])   (pre-scaled layer-0 operand)
__global__ void k_prescale(const float* __restrict__ emb) {
    int i = blockIdx.x * blockDim.x + threadIdx.x;   // over NN*32 half2 elems
    if (i >= NN * 32) return;
    int node = i >> 5;
    float dv = g_dinv[node];
    float2 e = ((const float2*)emb)[i];
    g_h0[i] = __floats2half2_rn(e.x * dv, e.y * dv);
}

// ---------------- SpMM: one warp per node, 4 edges per LDG.128 ---------------
// lane = group(0..3: edge-in-chunk) x sub(0..7: 16B row segment)
// s = sum_{e: dst=v} y_{l-1}[col_e];  y_l[v] = half(dinv^2 * s)
template<int LAYER>
__global__ void k_spmm() {
    int node = (blockIdx.x * blockDim.x + threadIdx.x) >> 5;
    if (node >= NN) return;
    int lane = threadIdx.x & 31;
    int group = lane >> 3;       // which of 4 edges in current chunk
    int sub   = lane & 7;        // which 16B segment of the 128B row

    const uint4* __restrict__ src4 = (const uint4*)
        ((LAYER == 0) ? g_h0 : (LAYER == 1) ? g_h1 : g_h2);
    uint4* __restrict__ dst4 = (uint4*)
        ((LAYER == 0) ? g_h1 : (LAYER == 1) ? g_h2 : g_h3);

    int beg = g_offs[node];
    int end = g_offs[node + 1];

    float a0=0.f,a1=0.f,a2=0.f,a3=0.f,a4=0.f,a5=0.f,a6=0.f,a7=0.f;

    for (int base = beg; base < end; base += 32) {
        int j = base + lane;
        int mycol = (j < end) ? g_col[j] : 0;    // coalesced: 1 LDG / 32 edges
        int cnt = end - base;
        if (cnt > 32) cnt = 32;

        int i = 0;
        #pragma unroll 2
        for (; i + 3 < cnt; i += 4) {
            int c = __shfl_sync(0xffffffffu, mycol, i + group);
            uint4 v = src4[c * 8 + sub];
            float2 f0 = __half22float2(*(const __half2*)&v.x);
            float2 f1 = __half22float2(*(const __half2*)&v.y);
            float2 f2 = __half22float2(*(const __half2*)&v.z);
            float2 f3 = __half22float2(*(const __half2*)&v.w);
            a0 += f0.x; a1 += f0.y; a2 += f1.x; a3 += f1.y;
            a4 += f2.x; a5 += f2.y; a6 += f3.x; a7 += f3.y;
        }
        if (i < cnt) {                            // remainder: 1..3 edges
            int e = i + group;
            int c = __shfl_sync(0xffffffffu, mycol, e & 31);
            if (e < cnt) {
                uint4 v = src4[c * 8 + sub];
                float2 f0 = __half22float2(*(const __half2*)&v.x);
                float2 f1 = __half22float2(*(const __half2*)&v.y);
                float2 f2 = __half22float2(*(const __half2*)&v.z);
                float2 f3 = __half22float2(*(const __half2*)&v.w);
                a0 += f0.x; a1 += f0.y; a2 += f1.x; a3 += f1.y;
                a4 += f2.x; a5 += f2.y; a6 += f3.x; a7 += f3.y;
            }
        }
    }

    // reduce partial sums across the 4 groups (same sub -> same dims)
    #pragma unroll
    for (int off = 8; off <= 16; off <<= 1) {
        a0 += __shfl_xor_sync(0xffffffffu, a0, off);
        a1 += __shfl_xor_sync(0xffffffffu, a1, off);
        a2 += __shfl_xor_sync(0xffffffffu, a2, off);
        a3 += __shfl_xor_sync(0xffffffffu, a3, off);
        a4 += __shfl_xor_sync(0xffffffffu, a4, off);
        a5 += __shfl_xor_sync(0xffffffffu, a5, off);
        a6 += __shfl_xor_sync(0xffffffffu, a6, off);
        a7 += __shfl_xor_sync(0xffffffffu, a7, off);
    }

    if (lane < 8) {                               // 8 lanes emit 128B row
        float dv = g_dinv[node];
        float d2 = dv * dv;
        __half2 h0 = __floats2half2_rn(d2 * a0, d2 * a1);
        __half2 h1 = __floats2half2_rn(d2 * a2, d2 * a3);
        __half2 h2 = __floats2half2_rn(d2 * a4, d2 * a5);
        __half2 h3 = __floats2half2_rn(d2 * a6, d2 * a7);
        uint4 o;
        o.x = *(const unsigned int*)&h0;
        o.y = *(const unsigned int*)&h1;
        o.z = *(const unsigned int*)&h2;
        o.w = *(const unsigned int*)&h3;
        dst4[node * 8 + sub] = o;
    }
}

// ---------------- epilogue ---------------------------------------------------
// r_l[v] = y_l[v] / dinv[v];  final = (emb + r1 + r2 + r3) / 4
__global__ void k_output(const int* __restrict__ users,
                         const int* __restrict__ pos,
                         const int* __restrict__ neg,
                         const float* __restrict__ emb,
                         float* __restrict__ out, int batch) {
    int warp = (blockIdx.x * blockDim.x + threadIdx.x) >> 5;
    if (warp >= batch) return;
    int lane = threadIdx.x & 31;

    int idx[3];
    idx[0] = users[warp];
    idx[1] = NU + pos[warp];
    idx[2] = NU + neg[warp];

    float part = 0.f;
    #pragma unroll
    for (int t = 0; t < 3; t++) {
        int v = idx[t];
        int o = v * 32 + lane;
        float sd = 1.0f / g_dinv[v];            // sqrt(deg)
        float2 e  = ((const float2*)emb)[o];
        float2 y1 = __half22float2(g_h1[o]);
        float2 y2 = __half22float2(g_h2[o]);
        float2 y3 = __half22float2(g_h3[o]);
        float fx = (e.x + (y1.x + y2.x + y3.x) * sd) * 0.25f;
        float fy = (e.y + (y1.y + y2.y + y3.y) * sd) * 0.25f;
        ((float2*)out)[(size_t)t * batch * 32 + (size_t)warp * 32 + lane] =
            make_float2(fx, fy);
        part += e.x * e.x + e.y * e.y;
    }

    #pragma unroll
    for (int off = 16; off > 0; off >>= 1)
        part += __shfl_down_sync(0xffffffffu, part, off);
    if (lane == 0)
        out[(size_t)3 * batch * D + warp] = part;
}

// ---------------- launch -----------------------------------------------------
extern "C" void kernel_launch(void* const* d_in, const int* in_sizes, int n_in,
                              void* d_out, int out_size) {
    const float* emb   = (const float*)d_in[0];
    const int*   eu    = (const int*)  d_in[1];
    const int*   ei    = (const int*)  d_in[2];
    const int*   users = (const int*)  d_in[3];
    const int*   pos   = (const int*)  d_in[4];
    const int*   neg   = (const int*)  d_in[5];
    int ne    = in_sizes[1];
    int batch = in_sizes[3];
    float* out = (float*)d_out;

    // 1) degrees
    k_zero_deg<<<(NN + 255) / 256, 256>>>();
    k_count_deg<<<(ne + 255) / 256, 256>>>(eu, ei, ne);

    // 2) CSR offsets (2-level scan, dinv fused into scan_a) + cursors
    k_scan_a<<<NB, 1024>>>(NN);
    k_scan_b<<<1, 1024>>>(NB, NN);
    k_scan_c<<<NB, 1024>>>(NN);

    // 3) CSR fill (cols only) + pre-scaled fp16 embedding
    k_fill_csr<<<(ne + 255) / 256, 256>>>(eu, ei, ne);
    k_prescale<<<(NN * 32 + 255) / 256, 256>>>(emb);

    // 4) three propagation layers (fp16 gathers, 4 edges per LDG.128)
    int spmm_blocks = (NN * 32 + 255) / 256;
    k_spmm<0><<<spmm_blocks, 256>>>();   // h0 -> h1
    k_spmm<1><<<spmm_blocks, 256>>>();   // h1 -> h2
    k_spmm<2><<<spmm_blocks, 256>>>();   // h2 -> h3

    // 5) epilogue: reconstruct r_l, fold, l2 norms
    k_output<<<(batch * 32 + 255) / 256, 256>>>(users, pos, neg, emb, out, batch);
}

// round 9
// speedup vs baseline: 1.7013x; 1.2227x over previous
#include <cuda_runtime.h>
#include <cuda_fp16.h>

#define NU 100000
#define NI 50000
#define NN 150000           // NU + NI
#define D  64
#define MAXE 1500000        // interactions
#define NBK 147             // ceil(NN / 1024)

// ---------------- scratch (static device globals) ---------------------------
// y_l = dinv^2 * s  (pre-scaled fp16 operand; r_l = y_l / dinv)
__device__ __half2 g_h0[NN * D / 2];   // layer-0 operand: half(emb * dinv)
__device__ __half2 g_h1[NN * D / 2];
__device__ __half2 g_h2[NN * D / 2];
__device__ int     g_deg [NN];
__device__ float   g_dinv[NN];
__device__ int     g_offs[NN];         // CSR slab start per node
__device__ int     g_cursor[NN];
__device__ int     g_col[2 * MAXE];    // CSR src index (weight-free)
__device__ int     g_tail;             // global slab allocator

// ---------------- setup ------------------------------------------------------
__global__ void k_zero_deg() {
    int i = blockIdx.x * blockDim.x + threadIdx.x;
    if (i < NN) g_deg[i] = 0;
    if (i == 0) g_tail = 0;
}

__global__ void k_count_deg(const int* __restrict__ eu,
                            const int* __restrict__ ei, int ne) {
    int e = blockIdx.x * blockDim.x + threadIdx.x;
    if (e >= ne) return;
    atomicAdd(&g_deg[eu[e]], 1);
    atomicAdd(&g_deg[NU + ei[e]], 1);
}

// Per-block scan + single atomic slab allocation; also computes dinv.
__global__ void k_alloc(int n) {
    __shared__ int sh[1024];
    __shared__ int base;
    int tid = threadIdx.x;
    int i = blockIdx.x * 1024 + tid;
    int v = (i < n) ? g_deg[i] : 0;
    if (i < n) g_dinv[i] = rsqrtf(v > 0 ? (float)v : 1.0f);
    sh[tid] = v;
    __syncthreads();
    for (int off = 1; off < 1024; off <<= 1) {
        int t = (tid >= off) ? sh[tid - off] : 0;
        __syncthreads();
        sh[tid] += t;
        __syncthreads();
    }
    if (tid == 1023) base = atomicAdd(&g_tail, sh[1023]);
    __syncthreads();
    if (i < n) {
        int o = base + sh[tid] - v;    // exclusive within block + slab base
        g_offs[i] = o;
        g_cursor[i] = o;
    }
}

// Fused: blocks [0, FB) fill CSR cols; blocks [FB, FB+PB) prescale h0.
__global__ void k_fill_prescale(const int* __restrict__ eu,
                                const int* __restrict__ ei, int ne,
                                const float* __restrict__ emb, int fb) {
    if ((int)blockIdx.x < fb) {
        int e = blockIdx.x * blockDim.x + threadIdx.x;
        if (e >= ne) return;
        int u  = eu[e];
        int it = NU + ei[e];
        int s1 = atomicAdd(&g_cursor[it], 1);
        g_col[s1] = u;                      // edge user -> item (dst=item)
        int s2 = atomicAdd(&g_cursor[u], 1);
        g_col[s2] = it;                     // edge item -> user (dst=user)
    } else {
        int i = (blockIdx.x - fb) * blockDim.x + threadIdx.x; // NN*32 half2
        if (i >= NN * 32) return;
        int node = i >> 5;
        float dv = g_dinv[node];
        float2 e2 = ((const float2*)emb)[i];
        g_h0[i] = __floats2half2_rn(e2.x * dv, e2.y * dv);
    }
}

// ---------------- SpMM: one warp per node, 4 edges per LDG.128 ---------------
// lane = group(0..3: edge-in-chunk) x sub(0..7: 16B row segment)
// s = sum_{e: dst=v} y_{l-1}[col_e];  y_l[v] = half(dinv^2 * s)
template<int LAYER>
__global__ void k_spmm() {
    int node = (blockIdx.x * blockDim.x + threadIdx.x) >> 5;
    if (node >= NN) return;
    int lane = threadIdx.x & 31;
    int group = lane >> 3;
    int sub   = lane & 7;

    const uint4* __restrict__ src4 = (const uint4*)((LAYER == 0) ? g_h0 : g_h1);
    uint4* __restrict__ dst4       = (uint4*)((LAYER == 0) ? g_h1 : g_h2);

    int beg = g_offs[node];
    int end = beg + g_deg[node];

    float a0=0.f,a1=0.f,a2=0.f,a3=0.f,a4=0.f,a5=0.f,a6=0.f,a7=0.f;

    for (int base = beg; base < end; base += 32) {
        int j = base + lane;
        int mycol = (j < end) ? g_col[j] : 0;    // coalesced: 1 LDG / 32 edges
        int cnt = end - base;
        if (cnt > 32) cnt = 32;

        int i = 0;
        #pragma unroll 2
        for (; i + 3 < cnt; i += 4) {
            int c = __shfl_sync(0xffffffffu, mycol, i + group);
            uint4 v = src4[c * 8 + sub];
            float2 f0 = __half22float2(*(const __half2*)&v.x);
            float2 f1 = __half22float2(*(const __half2*)&v.y);
            float2 f2 = __half22float2(*(const __half2*)&v.z);
            float2 f3 = __half22float2(*(const __half2*)&v.w);
            a0 += f0.x; a1 += f0.y; a2 += f1.x; a3 += f1.y;
            a4 += f2.x; a5 += f2.y; a6 += f3.x; a7 += f3.y;
        }
        if (i < cnt) {
            int e = i + group;
            int c = __shfl_sync(0xffffffffu, mycol, e & 31);
            if (e < cnt) {
                uint4 v = src4[c * 8 + sub];
                float2 f0 = __half22float2(*(const __half2*)&v.x);
                float2 f1 = __half22float2(*(const __half2*)&v.y);
                float2 f2 = __half22float2(*(const __half2*)&v.z);
                float2 f3 = __half22float2(*(const __half2*)&v.w);
                a0 += f0.x; a1 += f0.y; a2 += f1.x; a3 += f1.y;
                a4 += f2.x; a5 += f2.y; a6 += f3.x; a7 += f3.y;
            }
        }
    }

    #pragma unroll
    for (int off = 8; off <= 16; off <<= 1) {
        a0 += __shfl_xor_sync(0xffffffffu, a0, off);
        a1 += __shfl_xor_sync(0xffffffffu, a1, off);
        a2 += __shfl_xor_sync(0xffffffffu, a2, off);
        a3 += __shfl_xor_sync(0xffffffffu, a3, off);
        a4 += __shfl_xor_sync(0xffffffffu, a4, off);
        a5 += __shfl_xor_sync(0xffffffffu, a5, off);
        a6 += __shfl_xor_sync(0xffffffffu, a6, off);
        a7 += __shfl_xor_sync(0xffffffffu, a7, off);
    }

    if (lane < 8) {
        float dv = g_dinv[node];
        float d2 = dv * dv;
        __half2 h0 = __floats2half2_rn(d2 * a0, d2 * a1);
        __half2 h1 = __floats2half2_rn(d2 * a2, d2 * a3);
        __half2 h2 = __floats2half2_rn(d2 * a4, d2 * a5);
        __half2 h3 = __floats2half2_rn(d2 * a6, d2 * a7);
        uint4 o;
        o.x = *(const unsigned int*)&h0;
        o.y = *(const unsigned int*)&h1;
        o.z = *(const unsigned int*)&h2;
        o.w = *(const unsigned int*)&h3;
        dst4[node * 8 + sub] = o;
    }
}

// ---------------- layer 3 (sampled nodes only) + epilogue --------------------
// One warp per output row (3*batch rows). Gathers neighbors from h2 (fp32 s),
// r3 = dinv*s; r1,r2 reconstructed from h1,h2; out=(emb+r1+r2+r3)/4.
// t==0 warps additionally compute the l2 norms.
__global__ void k_spmm_out(const int* __restrict__ users,
                           const int* __restrict__ pos,
                           const int* __restrict__ neg,
                           const float* __restrict__ emb,
                           float* __restrict__ out, int batch) {
    int w = (blockIdx.x * blockDim.x + threadIdx.x) >> 5;
    if (w >= 3 * batch) return;
    int t = w / batch;
    int b = w - t * batch;
    int lane = threadIdx.x & 31;
    int group = lane >> 3;
    int sub   = lane & 7;

    int node = (t == 0) ? users[b] : (t == 1) ? (NU + pos[b]) : (NU + neg[b]);

    const uint4* __restrict__ src4 = (const uint4*)g_h2;
    int beg = g_offs[node];
    int end = beg + g_deg[node];

    float a0=0.f,a1=0.f,a2=0.f,a3=0.f,a4=0.f,a5=0.f,a6=0.f,a7=0.f;
    for (int base = beg; base < end; base += 32) {
        int j = base + lane;
        int mycol = (j < end) ? g_col[j] : 0;
        int cnt = end - base;
        if (cnt > 32) cnt = 32;
        for (int i = 0; i < cnt; i += 4) {
            int e = i + group;
            int c = __shfl_sync(0xffffffffu, mycol, e & 31);
            if (e < cnt) {
                uint4 v = src4[c * 8 + sub];
                float2 f0 = __half22float2(*(const __half2*)&v.x);
                float2 f1 = __half22float2(*(const __half2*)&v.y);
                float2 f2 = __half22float2(*(const __half2*)&v.z);
                float2 f3 = __half22float2(*(const __half2*)&v.w);
                a0 += f0.x; a1 += f0.y; a2 += f1.x; a3 += f1.y;
                a4 += f2.x; a5 += f2.y; a6 += f3.x; a7 += f3.y;
            }
        }
    }
    #pragma unroll
    for (int off = 8; off <= 16; off <<= 1) {
        a0 += __shfl_xor_sync(0xffffffffu, a0, off);
        a1 += __shfl_xor_sync(0xffffffffu, a1, off);
        a2 += __shfl_xor_sync(0xffffffffu, a2, off);
        a3 += __shfl_xor_sync(0xffffffffu, a3, off);
        a4 += __shfl_xor_sync(0xffffffffu, a4, off);
        a5 += __shfl_xor_sync(0xffffffffu, a5, off);
        a6 += __shfl_xor_sync(0xffffffffu, a6, off);
        a7 += __shfl_xor_sync(0xffffffffu, a7, off);
    }

    float l2part = 0.f;
    if (lane < 8) {
        float dv = g_dinv[node];
        float sd = 1.0f / dv;                   // sqrt(deg)
        // emb segment: 8 fp32 dims = 2 float4
        const float4* e4 = (const float4*)(emb + (size_t)node * D + sub * 8);
        float4 e0 = e4[0], e1 = e4[1];
        // y1, y2 segments (8 halves each)
        uint4 y1v = ((const uint4*)g_h1)[node * 8 + sub];
        uint4 y2v = ((const uint4*)g_h2)[node * 8 + sub];
        float2 p0 = __half22float2(*(const __half2*)&y1v.x);
        float2 p1 = __half22float2(*(const __half2*)&y1v.y);
        float2 p2 = __half22float2(*(const __half2*)&y1v.z);
        float2 p3 = __half22float2(*(const __half2*)&y1v.w);
        float2 q0 = __half22float2(*(const __half2*)&y2v.x);
        float2 q1 = __half22float2(*(const __half2*)&y2v.y);
        float2 q2 = __half22float2(*(const __half2*)&y2v.z);
        float2 q3 = __half22float2(*(const __half2*)&y2v.w);

        float4 o0, o1;
        o0.x = (e0.x + sd * (p0.x + q0.x) + dv * a0) * 0.25f;
        o0.y = (e0.y + sd * (p0.y + q0.y) + dv * a1) * 0.25f;
        o0.z = (e0.z + sd * (p1.x + q1.x) + dv * a2) * 0.25f;
        o0.w = (e0.w + sd * (p1.y + q1.y) + dv * a3) * 0.25f;
        o1.x = (e1.x + sd * (p2.x + q2.x) + dv * a4) * 0.25f;
        o1.y = (e1.y + sd * (p2.y + q2.y) + dv * a5) * 0.25f;
        o1.z = (e1.z + sd * (p3.x + q3.x) + dv * a6) * 0.25f;
        o1.w = (e1.w + sd * (p3.y + q3.y) + dv * a7) * 0.25f;
        float4* od = (float4*)(out + (size_t)t * batch * D + (size_t)b * D + sub * 8);
        od[0] = o0;
        od[1] = o1;

        if (t == 0) {
            // l2 needs emb of u (have it), p, n
            int pn = NU + pos[b];
            int nn = NU + neg[b];
            const float4* pp = (const float4*)(emb + (size_t)pn * D + sub * 8);
            const float4* np = (const float4*)(emb + (size_t)nn * D + sub * 8);
            float4 pe0 = pp[0], pe1 = pp[1];
            float4 ne0 = np[0], ne1 = np[1];
            l2part = e0.x*e0.x + e0.y*e0.y + e0.z*e0.z + e0.w*e0.w
                   + e1.x*e1.x + e1.y*e1.y + e1.z*e1.z + e1.w*e1.w
                   + pe0.x*pe0.x + pe0.y*pe0.y + pe0.z*pe0.z + pe0.w*pe0.w
                   + pe1.x*pe1.x + pe1.y*pe1.y + pe1.z*pe1.z + pe1.w*pe1.w
                   + ne0.x*ne0.x + ne0.y*ne0.y + ne0.z*ne0.z + ne0.w*ne0.w
                   + ne1.x*ne1.x + ne1.y*ne1.y + ne1.z*ne1.z + ne1.w*ne1.w;
        }
    }
    if (t == 0) {
        // reduce l2part across lanes 0..7
        l2part += __shfl_down_sync(0xffffffffu, l2part, 4);
        l2part += __shfl_down_sync(0xffffffffu, l2part, 2);
        l2part += __shfl_down_sync(0xffffffffu, l2part, 1);
        if (lane == 0)
            out[(size_t)3 * batch * D + b] = l2part;
    }
}

// ---------------- launch -----------------------------------------------------
extern "C" void kernel_launch(void* const* d_in, const int* in_sizes, int n_in,
                              void* d_out, int out_size) {
    const float* emb   = (const float*)d_in[0];
    const int*   eu    = (const int*)  d_in[1];
    const int*   ei    = (const int*)  d_in[2];
    const int*   users = (const int*)  d_in[3];
    const int*   pos   = (const int*)  d_in[4];
    const int*   neg   = (const int*)  d_in[5];
    int ne    = in_sizes[1];
    int batch = in_sizes[3];
    float* out = (float*)d_out;

    // 1) degrees
    k_zero_deg<<<(NN + 255) / 256, 256>>>();
    k_count_deg<<<(ne + 255) / 256, 256>>>(eu, ei, ne);

    // 2) slab allocation (block scan + one atomic) + dinv + cursors
    k_alloc<<<NBK, 1024>>>(NN);

    // 3) CSR fill + prescaled fp16 embedding (fused launch)
    int fb = (ne + 255) / 256;
    int pb = (NN * 32 + 255) / 256;
    k_fill_prescale<<<fb + pb, 256>>>(eu, ei, ne, emb, fb);

    // 4) two full-graph propagation layers
    int spmm_blocks = (NN * 32 + 255) / 256;
    k_spmm<0><<<spmm_blocks, 256>>>();   // h0 -> h1
    k_spmm<1><<<spmm_blocks, 256>>>();   // h1 -> h2

    // 5) layer 3 only at sampled nodes, fused with epilogue + l2
    int ow = 3 * batch;
    k_spmm_out<<<(ow * 32 + 255) / 256, 256>>>(users, pos, neg, emb, out, batch);
}